// round 1
// baseline (speedup 1.0000x reference)
#include <cuda_runtime.h>

// Problem constants
#define K   8
#define D   16
#define NN  32
#define TT  200
#define BB  2048
#define BT  (BB*TT)          // 409600
#define LOG2PI 1.8378770664093453f

// Padded shared strides (floats) chosen so 8 states map to disjoint banks:
// stride % 32 == 4 for the matrix tiles (16B chunks per state cover all 32 banks)
#define ES  516              // emission state stride (N*D=512 + 4)
#define AS  260              // dynamics state stride (D*D=256 + 4)
#define EMP 33               // float2 per-n params stride
#define DYP 17               // float2 per-d params stride

// Per-(b,t) log-prob scratch (static device global: allocation-free)
__device__ float g_lp[BT];

__device__ __forceinline__ float dot16(const float* __restrict__ row,
                                       const float z0, const float z1, const float z2, const float z3,
                                       const float z4, const float z5, const float z6, const float z7,
                                       const float z8, const float z9, const float z10, const float z11,
                                       const float z12, const float z13, const float z14, const float z15) {
    const float4* c4 = reinterpret_cast<const float4*>(row);
    float4 c0 = c4[0], c1 = c4[1], c2 = c4[2], c3 = c4[3];
    float p0 = c0.x * z0;  p0 = fmaf(c0.y, z1,  p0); p0 = fmaf(c0.z, z2,  p0); p0 = fmaf(c0.w, z3,  p0);
    float p1 = c1.x * z4;  p1 = fmaf(c1.y, z5,  p1); p1 = fmaf(c1.z, z6,  p1); p1 = fmaf(c1.w, z7,  p1);
    float p2 = c2.x * z8;  p2 = fmaf(c2.y, z9,  p2); p2 = fmaf(c2.z, z10, p2); p2 = fmaf(c2.w, z11, p2);
    float p3 = c3.x * z12; p3 = fmaf(c3.y, z13, p3); p3 = fmaf(c3.z, z14, p3); p3 = fmaf(c3.w, z15, p3);
    return (p0 + p1) + (p2 + p3);
}

#define Z_ALL z[0],z[1],z[2],z[3],z[4],z[5],z[6],z[7],z[8],z[9],z[10],z[11],z[12],z[13],z[14],z[15]
#define ZP_ALL zp[0],zp[1],zp[2],zp[3],zp[4],zp[5],zp[6],zp[7],zp[8],zp[9],zp[10],zp[11],zp[12],zp[13],zp[14],zp[15]

__global__ __launch_bounds__(256)
void stage1_kernel(const int*   __restrict__ ds,        // (B,T)
                   const float* __restrict__ cont,      // (B,T,D)
                   const float* __restrict__ obs,       // (B,T,N)
                   const float* __restrict__ init_logits,   // (K,)
                   const float* __restrict__ init_locs,     // (K,D)
                   const float* __restrict__ init_ls,       // (K,D)
                   const float* __restrict__ trans_logits,  // (K,K)
                   const float* __restrict__ dynM,          // (K,D,D)
                   const float* __restrict__ dynOff,        // (K,D)
                   const float* __restrict__ dynLS,         // (K,D)  raw scale!
                   const float* __restrict__ emM,           // (K,N,D)
                   const float* __restrict__ emOff,         // (K,N)
                   const float* __restrict__ emLS)          // (K,N)  scale = exp
{
    __shared__ float  sC[K * ES];     // C' = C * exp(-em_ls), row-padded by state
    __shared__ float  sA[K * AS];     // A' = A / dyn_scale
    __shared__ float2 sEm[K * EMP];   // (alpha, beta) per (s,n)
    __shared__ float2 sDy[K * DYP];   // (alpha, beta) per (s,d)
    __shared__ float2 sIn[K * DYP];   // init (a, b) per (s,d)
    __shared__ float  sTr[K * K];     // log-softmax transitions
    __shared__ float  sC0[K];         // t==0 per-state constant
    __shared__ float  sCT[K];         // t>0  per-state constant

    const int tid = threadIdx.x;

    // ---- preprocess params into shared (redundant per block; tiny) ----
    for (int i = tid; i < K * NN * D; i += 256) {
        int s = i >> 9;                // /512
        int r = i & 511;
        int n = r >> 4;
        float a = expf(-emLS[s * NN + n]);
        sC[s * ES + r] = emM[i] * a;
    }
    for (int i = tid; i < K * D * D; i += 256) {
        int s = i >> 8;
        int r = i & 255;
        int d = r >> 4;
        sA[s * AS + r] = dynM[i] / dynLS[s * D + d];
    }
    if (tid < K * NN) {
        int s = tid >> 5, n = tid & 31;
        float a = expf(-emLS[tid]);
        sEm[s * EMP + n] = make_float2(a, emOff[tid] * a);
    }
    if (tid < K * D) {
        int s = tid >> 4, d = tid & 15;
        float a = 1.0f / dynLS[tid];
        sDy[s * DYP + d] = make_float2(a, dynOff[tid] * a);
        float ai = expf(-init_ls[tid]);
        sIn[s * DYP + d] = make_float2(ai, init_locs[tid] * ai);
    }
    if (tid < K * K) {
        int sp = tid >> 3;
        float m = -1e30f;
        for (int k = 0; k < K; k++) m = fmaxf(m, trans_logits[sp * K + k]);
        float sum = 0.0f;
        for (int k = 0; k < K; k++) sum += expf(trans_logits[sp * K + k] - m);
        sTr[tid] = trans_logits[tid] - m - logf(sum);
    }
    if (tid < K) {
        int s = tid;
        float emc = -16.0f * LOG2PI;                       // -(N/2) log 2pi
        for (int n = 0; n < NN; n++) emc -= emLS[s * NN + n];
        float dync = -8.0f * LOG2PI;                       // -(D/2) log 2pi
        for (int d = 0; d < D; d++) dync -= logf(dynLS[s * D + d]);
        float initc = -8.0f * LOG2PI;
        for (int d = 0; d < D; d++) initc -= init_ls[s * D + d];
        float m = -1e30f;
        for (int k = 0; k < K; k++) m = fmaxf(m, init_logits[k]);
        float sum = 0.0f;
        for (int k = 0; k < K; k++) sum += expf(init_logits[k] - m);
        sC0[s] = (init_logits[s] - m - logf(sum)) + initc + emc;
        sCT[s] = emc + dync;
    }
    __syncthreads();

    // ---- main: one thread per (b,t) ----
    const int gid = blockIdx.x * 256 + tid;
    if (gid >= BT) return;
    const int b = gid / TT;
    const int t = gid - b * TT;
    const int s = ds[gid];

    // load z_t (16 floats) into registers
    float z[16];
    {
        const float4* z4 = reinterpret_cast<const float4*>(cont) + gid * 4;
        float4 v;
        v = z4[0]; z[0] = v.x; z[1] = v.y; z[2]  = v.z; z[3]  = v.w;
        v = z4[1]; z[4] = v.x; z[5] = v.y; z[6]  = v.z; z[7]  = v.w;
        v = z4[2]; z[8] = v.x; z[9] = v.y; z[10] = v.z; z[11] = v.w;
        v = z4[3]; z[12] = v.x; z[13] = v.y; z[14] = v.z; z[15] = v.w;
    }

    float acc = 0.0f;   // sum of y^2
    float lp;

    // ---- emission term (all t) ----
    {
        const float*  Cb = sC + s * ES;
        const float2* Eb = sEm + s * EMP;
        const float4* o4 = reinterpret_cast<const float4*>(obs) + gid * 8;
        #pragma unroll 2
        for (int n4 = 0; n4 < 8; n4++) {
            float4 o = o4[n4];
            #pragma unroll
            for (int k = 0; k < 4; k++) {
                int n = n4 * 4 + k;
                float2 ab = Eb[n];
                float dv = dot16(Cb + n * 16, Z_ALL);
                float on = (&o.x)[k];
                float y = fmaf(on, ab.x, -ab.y) - dv;
                acc = fmaf(y, y, acc);
            }
        }
    }

    if (t == 0) {
        // ---- init term ----
        lp = sC0[s];
        const float2* Ib = sIn + s * DYP;
        #pragma unroll
        for (int d = 0; d < D; d++) {
            float2 ab = Ib[d];
            float y = fmaf(z[d], ab.x, -ab.y);
            acc = fmaf(y, y, acc);
        }
    } else {
        // ---- transition + dynamics term ----
        const int sp = ds[gid - 1];
        lp = sCT[s] + sTr[sp * K + s];
        float zp[16];
        {
            const float4* p4 = reinterpret_cast<const float4*>(cont) + (gid - 1) * 4;
            float4 v;
            v = p4[0]; zp[0] = v.x; zp[1] = v.y; zp[2]  = v.z; zp[3]  = v.w;
            v = p4[1]; zp[4] = v.x; zp[5] = v.y; zp[6]  = v.z; zp[7]  = v.w;
            v = p4[2]; zp[8] = v.x; zp[9] = v.y; zp[10] = v.z; zp[11] = v.w;
            v = p4[3]; zp[12] = v.x; zp[13] = v.y; zp[14] = v.z; zp[15] = v.w;
        }
        const float*  Ab = sA + s * AS;
        const float2* Db = sDy + s * DYP;
        #pragma unroll
        for (int d = 0; d < D; d++) {
            float2 ab = Db[d];
            float dv = dot16(Ab + d * 16, ZP_ALL);
            float y = fmaf(z[d], ab.x, -ab.y) - dv;
            acc = fmaf(y, y, acc);
        }
    }

    g_lp[gid] = lp - 0.5f * acc;
}

// Stage 2: deterministic per-b reduction of 200 timestep terms. One warp per b.
__global__ __launch_bounds__(128)
void stage2_kernel(float* __restrict__ out)
{
    const int b = blockIdx.x * 4 + (threadIdx.x >> 5);
    const int lane = threadIdx.x & 31;
    const float* base = g_lp + b * TT;
    float sum = 0.0f;
    for (int t = lane; t < TT; t += 32) sum += base[t];
    #pragma unroll
    for (int o = 16; o > 0; o >>= 1) sum += __shfl_xor_sync(0xFFFFFFFFu, sum, o);
    if (lane == 0) out[b] = sum;
}

extern "C" void kernel_launch(void* const* d_in, const int* in_sizes, int n_in,
                              void* d_out, int out_size)
{
    const int*   ds    = (const int*)  d_in[0];
    const float* cont  = (const float*)d_in[1];
    const float* obs   = (const float*)d_in[2];
    const float* il    = (const float*)d_in[3];
    const float* iloc  = (const float*)d_in[4];
    const float* ils   = (const float*)d_in[5];
    const float* trl   = (const float*)d_in[6];
    const float* dynM  = (const float*)d_in[7];
    const float* dynO  = (const float*)d_in[8];
    const float* dynS  = (const float*)d_in[9];
    const float* emM   = (const float*)d_in[10];
    const float* emO   = (const float*)d_in[11];
    const float* emS   = (const float*)d_in[12];
    float* out = (float*)d_out;

    stage1_kernel<<<BT / 256, 256>>>(ds, cont, obs, il, iloc, ils, trl,
                                     dynM, dynO, dynS, emM, emO, emS);
    stage2_kernel<<<BB / 4, 128>>>(out);
}

// round 2
// speedup vs baseline: 1.2225x; 1.2225x over previous
#include <cuda_runtime.h>

// Problem constants
#define K   8
#define D   16
#define NN  32
#define TT  200
#define BB  2048
#define BT  (BB*TT)          // 409600
#define LOG2PI 1.8378770664093453f

// Padded strides (floats) so 8 states map to disjoint banks
#define ES  516              // emission matrix state stride (512 + 4)
#define AS  260              // dynamics matrix state stride (256 + 4)
#define EA_S 34              // emission alpha/negbeta state stride (32 + 2)
#define DYP 17               // dyn/init float2 per-state stride

// Packed param image offsets (floats)
#define OFF_C   0                    // K*ES   = 4128
#define OFF_A   4128                 // K*AS   = 2080
#define OFF_EA  6208                 // K*34   = 272
#define OFF_EB  6480                 // K*34   = 272
#define OFF_DY  6752                 // K*17*2 = 272
#define OFF_IN  7024                 // 272
#define OFF_TR  7296                 // 64
#define OFF_C0  7360                 // 8
#define OFF_CT  7368                 // 8
#define P_TOTAL 7376                 // divisible by 4

__device__ __align__(16) float g_params[P_TOTAL];
__device__ float g_lp[BT];

typedef unsigned long long ull;

#define PACK2(d, lo, hi)  asm("mov.b64 %0, {%1, %2};" : "=l"(d) : "f"(lo), "f"(hi))
#define FMA2(d, a, b, c)  asm("fma.rn.f32x2 %0, %1, %2, %3;" : "=l"(d) : "l"(a), "l"(b), "l"(c))
#define ADD2(d, a, b)     asm("add.rn.f32x2 %0, %1, %2;" : "=l"(d) : "l"(a), "l"(b))
#define UNPACK2(lo, hi, s) asm("mov.b64 {%0, %1}, %2;" : "=f"(lo), "=f"(hi) : "l"(s))

// negated dot over 16 elements: returns -(row . z)
__device__ __forceinline__ float dot16n(const float* __restrict__ row, const ull* __restrict__ z2) {
    const ulonglong2* c2 = reinterpret_cast<const ulonglong2*>(row);
    ulonglong2 a = c2[0], b = c2[1], c = c2[2], e = c2[3];
    ull acc0, acc1;
    asm("mul.rn.f32x2 %0, %1, %2;" : "=l"(acc0) : "l"(a.x), "l"(z2[0]));
    asm("mul.rn.f32x2 %0, %1, %2;" : "=l"(acc1) : "l"(a.y), "l"(z2[1]));
    FMA2(acc0, b.x, z2[2], acc0);
    FMA2(acc1, b.y, z2[3], acc1);
    FMA2(acc0, c.x, z2[4], acc0);
    FMA2(acc1, c.y, z2[5], acc1);
    FMA2(acc0, e.x, z2[6], acc0);
    FMA2(acc1, e.y, z2[7], acc1);
    ADD2(acc0, acc0, acc1);
    float lo, hi; UNPACK2(lo, hi, acc0);
    return __fadd_rn(-lo, -hi);
}

// ---------- prep: one block computes the packed param image ----------
__global__ __launch_bounds__(256)
void prep_kernel(const float* __restrict__ init_logits,
                 const float* __restrict__ init_locs,
                 const float* __restrict__ init_ls,
                 const float* __restrict__ trans_logits,
                 const float* __restrict__ dynM,
                 const float* __restrict__ dynOff,
                 const float* __restrict__ dynLS,
                 const float* __restrict__ emM,
                 const float* __restrict__ emOff,
                 const float* __restrict__ emLS)
{
    const int tid = threadIdx.x;
    for (int i = tid; i < K * NN * D; i += 256) {
        int s = i >> 9, r = i & 511, n = r >> 4;
        g_params[OFF_C + s * ES + r] = emM[i] * expf(-emLS[s * NN + n]);
    }
    for (int i = tid; i < K * D * D; i += 256) {
        int s = i >> 8, r = i & 255, d = r >> 4;
        g_params[OFF_A + s * AS + r] = dynM[i] / dynLS[s * D + d];
    }
    if (tid < K * NN) {
        int s = tid >> 5, n = tid & 31;
        float a = expf(-emLS[tid]);
        g_params[OFF_EA + s * EA_S + n] = a;
        g_params[OFF_EB + s * EA_S + n] = -emOff[tid] * a;
    }
    if (tid < K * D) {
        int s = tid >> 4, d = tid & 15;
        float a = 1.0f / dynLS[tid];
        g_params[OFF_DY + (s * DYP + d) * 2]     = a;
        g_params[OFF_DY + (s * DYP + d) * 2 + 1] = -dynOff[tid] * a;
        float ai = expf(-init_ls[tid]);
        g_params[OFF_IN + (s * DYP + d) * 2]     = ai;
        g_params[OFF_IN + (s * DYP + d) * 2 + 1] = -init_locs[tid] * ai;
    }
    if (tid < K * K) {
        int sp = tid >> 3;
        float m = -1e30f;
        for (int k = 0; k < K; k++) m = fmaxf(m, trans_logits[sp * K + k]);
        float sum = 0.0f;
        for (int k = 0; k < K; k++) sum += expf(trans_logits[sp * K + k] - m);
        g_params[OFF_TR + tid] = trans_logits[tid] - m - logf(sum);
    }
    if (tid < K) {
        int s = tid;
        float emc = -16.0f * LOG2PI;
        for (int n = 0; n < NN; n++) emc -= emLS[s * NN + n];
        float dync = -8.0f * LOG2PI;
        for (int d = 0; d < D; d++) dync -= logf(dynLS[s * D + d]);
        float initc = -8.0f * LOG2PI;
        for (int d = 0; d < D; d++) initc -= init_ls[s * D + d];
        float m = -1e30f;
        for (int k = 0; k < K; k++) m = fmaxf(m, init_logits[k]);
        float sum = 0.0f;
        for (int k = 0; k < K; k++) sum += expf(init_logits[k] - m);
        g_params[OFF_C0 + s] = (init_logits[s] - m - logf(sum)) + initc + emc;
        g_params[OFF_CT + s] = emc + dync;
    }
}

// ---------- stage 1: one thread per (b,t) ----------
__global__ __launch_bounds__(256)
void stage1_kernel(const int*   __restrict__ ds,
                   const float* __restrict__ cont,
                   const float* __restrict__ obs)
{
    __shared__ __align__(16) float sP[P_TOTAL];
    const int tid = threadIdx.x;
    {
        const float4* src = reinterpret_cast<const float4*>(g_params);
        float4* dst = reinterpret_cast<float4*>(sP);
        #pragma unroll
        for (int i = 0; i < P_TOTAL / 4 / 256 + 1; i++) {
            int idx = tid + i * 256;
            if (idx < P_TOTAL / 4) dst[idx] = src[idx];
        }
    }
    __syncthreads();

    const int gid = blockIdx.x * 256 + tid;
    const int b = gid / TT;
    const int t = gid - b * TT;
    const int s = ds[gid];

    // z_t packed into 8 f32x2 regs
    ull z2[8];
    {
        const float4* z4 = reinterpret_cast<const float4*>(cont) + gid * 4;
        #pragma unroll
        for (int i = 0; i < 4; i++) {
            float4 v = z4[i];
            PACK2(z2[i * 2],     v.x, v.y);
            PACK2(z2[i * 2 + 1], v.z, v.w);
        }
    }

    float accs = 0.0f;                 // scalar y^2 accumulator (dyn/init)
    ull acc2; { float zf = 0.0f; PACK2(acc2, zf, zf); }
    float lp;

    // ---- emission (all t), packed over n-pairs ----
    {
        const float* Cb = sP + OFF_C + s * ES;
        const ull* EA = reinterpret_cast<const ull*>(sP + OFF_EA + s * EA_S);
        const ull* EB = reinterpret_cast<const ull*>(sP + OFF_EB + s * EA_S);
        const float4* o4 = reinterpret_cast<const float4*>(obs) + gid * 8;
        #pragma unroll 4
        for (int n4 = 0; n4 < 8; n4++) {
            float4 o = o4[n4];
            int n = n4 * 4;
            // pair (n, n+1)
            float nd0 = dot16n(Cb + n * 16, z2);
            float nd1 = dot16n(Cb + (n + 1) * 16, z2);
            ull o01, nd01, y01;
            PACK2(o01, o.x, o.y);
            PACK2(nd01, nd0, nd1);
            FMA2(y01, o01, EA[n4 * 2], EB[n4 * 2]);
            ADD2(y01, y01, nd01);
            FMA2(acc2, y01, y01, acc2);
            // pair (n+2, n+3)
            float nd2 = dot16n(Cb + (n + 2) * 16, z2);
            float nd3 = dot16n(Cb + (n + 3) * 16, z2);
            ull o23, nd23, y23;
            PACK2(o23, o.z, o.w);
            PACK2(nd23, nd2, nd3);
            FMA2(y23, o23, EA[n4 * 2 + 1], EB[n4 * 2 + 1]);
            ADD2(y23, y23, nd23);
            FMA2(acc2, y23, y23, acc2);
        }
    }

    if (t == 0) {
        lp = sP[OFF_C0 + s];
        const float2* Ib = reinterpret_cast<const float2*>(sP + OFF_IN) + s * DYP;
        const float* zf = reinterpret_cast<const float*>(z2);
        #pragma unroll
        for (int d = 0; d < D; d++) {
            float2 ab = Ib[d];
            float y = fmaf(zf[d], ab.x, ab.y);
            accs = fmaf(y, y, accs);
        }
    } else {
        const int sp = ds[gid - 1];
        lp = sP[OFF_CT + s] + sP[OFF_TR + sp * K + s];
        ull zp2[8];
        {
            const float4* p4 = reinterpret_cast<const float4*>(cont) + (gid - 1) * 4;
            #pragma unroll
            for (int i = 0; i < 4; i++) {
                float4 v = p4[i];
                PACK2(zp2[i * 2],     v.x, v.y);
                PACK2(zp2[i * 2 + 1], v.z, v.w);
            }
        }
        const float* Ab = sP + OFF_A + s * AS;
        const float2* Db = reinterpret_cast<const float2*>(sP + OFF_DY) + s * DYP;
        const float* zf = reinterpret_cast<const float*>(z2);
        #pragma unroll
        for (int d = 0; d < D; d++) {
            float2 ab = Db[d];
            float nd = dot16n(Ab + d * 16, zp2);
            float y = fmaf(zf[d], ab.x, ab.y) + nd;
            accs = fmaf(y, y, accs);
        }
    }

    float lo, hi; UNPACK2(lo, hi, acc2);
    g_lp[gid] = lp - 0.5f * ((accs + lo) + hi);
}

// ---------- stage 2: one warp per b, 7 independent loads ----------
__global__ __launch_bounds__(256)
void stage2_kernel(float* __restrict__ out)
{
    const int b = blockIdx.x * 8 + (threadIdx.x >> 5);
    const int lane = threadIdx.x & 31;
    const float* base = g_lp + b * TT;
    float v[7];
    #pragma unroll
    for (int k = 0; k < 7; k++) {
        int t = lane + k * 32;
        v[k] = (t < TT) ? base[t] : 0.0f;
    }
    float sum = ((v[0] + v[1]) + (v[2] + v[3])) + ((v[4] + v[5]) + v[6]);
    #pragma unroll
    for (int o = 16; o > 0; o >>= 1) sum += __shfl_xor_sync(0xFFFFFFFFu, sum, o);
    if (lane == 0) out[b] = sum;
}

extern "C" void kernel_launch(void* const* d_in, const int* in_sizes, int n_in,
                              void* d_out, int out_size)
{
    const int*   ds    = (const int*)  d_in[0];
    const float* cont  = (const float*)d_in[1];
    const float* obs   = (const float*)d_in[2];
    const float* il    = (const float*)d_in[3];
    const float* iloc  = (const float*)d_in[4];
    const float* ils   = (const float*)d_in[5];
    const float* trl   = (const float*)d_in[6];
    const float* dynM  = (const float*)d_in[7];
    const float* dynO  = (const float*)d_in[8];
    const float* dynS  = (const float*)d_in[9];
    const float* emM   = (const float*)d_in[10];
    const float* emO   = (const float*)d_in[11];
    const float* emS   = (const float*)d_in[12];
    float* out = (float*)d_out;

    prep_kernel<<<1, 256>>>(il, iloc, ils, trl, dynM, dynO, dynS, emM, emO, emS);
    stage1_kernel<<<BT / 256, 256>>>(ds, cont, obs);
    stage2_kernel<<<BB / 8, 256>>>(out);
}

// round 3
// speedup vs baseline: 1.3447x; 1.1000x over previous
#include <cuda_runtime.h>

// Problem constants
#define K   8
#define D   16
#define NN  32
#define TT  200
#define BB  2048
#define BT  (BB*TT)          // 409600
#define LOG2PI 1.8378770664093453f

// Padded strides (floats) so 8 states map to disjoint banks
#define ES  516              // emission matrix state stride (512 + 4)
#define AS  260              // dynamics matrix state stride (256 + 4)
#define EA_S 34              // emission alpha/negbeta state stride
#define DYP 17               // dyn/init float2 per-state stride

// Packed param image offsets (floats)
#define OFF_C   0                    // K*ES   = 4128
#define OFF_A   4128                 // K*AS   = 2080
#define OFF_EA  6208                 // K*34   = 272
#define OFF_EB  6480                 // K*34   = 272
#define OFF_DY  6752                 // K*17*2 = 272
#define OFF_IN  7024                 // 272
#define OFF_TR  7296                 // 64
#define OFF_C0  7360                 // 8
#define OFF_CT  7368                 // 8
#define P_TOTAL 7376

__device__ __align__(16) float g_params[P_TOTAL];
__device__ float g_lp[BT];

typedef unsigned long long ull;

#define PACK2(d, lo, hi)  asm("mov.b64 %0, {%1, %2};" : "=l"(d) : "f"(lo), "f"(hi))
#define FMA2(d, a, b, c)  asm("fma.rn.f32x2 %0, %1, %2, %3;" : "=l"(d) : "l"(a), "l"(b), "l"(c))
#define MUL2(d, a, b)     asm("mul.rn.f32x2 %0, %1, %2;" : "=l"(d) : "l"(a), "l"(b))
#define ADD2(d, a, b)     asm("add.rn.f32x2 %0, %1, %2;" : "=l"(d) : "l"(a), "l"(b))
#define UNPACK2(lo, hi, s) asm("mov.b64 {%0, %1}, %2;" : "=f"(lo), "=f"(hi) : "l"(s))

// negated dot over 16 elements: returns -(row . z)
__device__ __forceinline__ float dot16n(const float* __restrict__ row, const ull* __restrict__ z2) {
    const ulonglong2* c2 = reinterpret_cast<const ulonglong2*>(row);
    ulonglong2 a = c2[0], b = c2[1], c = c2[2], e = c2[3];
    ull acc0, acc1;
    MUL2(acc0, a.x, z2[0]);
    MUL2(acc1, a.y, z2[1]);
    FMA2(acc0, b.x, z2[2], acc0);
    FMA2(acc1, b.y, z2[3], acc1);
    FMA2(acc0, c.x, z2[4], acc0);
    FMA2(acc1, c.y, z2[5], acc1);
    FMA2(acc0, e.x, z2[6], acc0);
    FMA2(acc1, e.y, z2[7], acc1);
    ADD2(acc0, acc0, acc1);
    float lo, hi; UNPACK2(lo, hi, acc0);
    return __fadd_rn(-lo, -hi);
}

// ---------- prep: one element per thread, fully parallel ----------
// gtid ranges: [0,4096) C | [4096,6144) A | [6144,6400) em a/b |
//              [6400,6528) dyn/init | [6528,6592) trans | [6592,6600) consts
__global__ __launch_bounds__(256)
void prep_kernel(const float* __restrict__ init_logits,
                 const float* __restrict__ init_locs,
                 const float* __restrict__ init_ls,
                 const float* __restrict__ trans_logits,
                 const float* __restrict__ dynM,
                 const float* __restrict__ dynOff,
                 const float* __restrict__ dynLS,
                 const float* __restrict__ emM,
                 const float* __restrict__ emOff,
                 const float* __restrict__ emLS)
{
    const int g = blockIdx.x * 256 + threadIdx.x;
    if (g < 4096) {
        int i = g;
        int s = i >> 9, r = i & 511, n = r >> 4;
        g_params[OFF_C + s * ES + r] = emM[i] * expf(-emLS[s * NN + n]);
    } else if (g < 6144) {
        int i = g - 4096;
        int s = i >> 8, r = i & 255, d = r >> 4;
        g_params[OFF_A + s * AS + r] = dynM[i] / dynLS[s * D + d];
    } else if (g < 6400) {
        int i = g - 6144;                 // K*NN
        int s = i >> 5, n = i & 31;
        float a = expf(-emLS[i]);
        g_params[OFF_EA + s * EA_S + n] = a;
        g_params[OFF_EB + s * EA_S + n] = -emOff[i] * a;
    } else if (g < 6528) {
        int i = g - 6400;                 // K*D
        int s = i >> 4, d = i & 15;
        float a = 1.0f / dynLS[i];
        g_params[OFF_DY + (s * DYP + d) * 2]     = a;
        g_params[OFF_DY + (s * DYP + d) * 2 + 1] = -dynOff[i] * a;
        float ai = expf(-init_ls[i]);
        g_params[OFF_IN + (s * DYP + d) * 2]     = ai;
        g_params[OFF_IN + (s * DYP + d) * 2 + 1] = -init_locs[i] * ai;
    } else if (g < 6592) {
        int i = g - 6528;                 // K*K
        int sp = i >> 3;
        float m = -1e30f;
        for (int k = 0; k < K; k++) m = fmaxf(m, trans_logits[sp * K + k]);
        float sum = 0.0f;
        for (int k = 0; k < K; k++) sum += expf(trans_logits[sp * K + k] - m);
        g_params[OFF_TR + i] = trans_logits[i] - m - logf(sum);
    } else if (g < 6600) {
        int s = g - 6592;                 // K
        float emc = -16.0f * LOG2PI;
        for (int n = 0; n < NN; n++) emc -= emLS[s * NN + n];
        float dync = -8.0f * LOG2PI;
        for (int d = 0; d < D; d++) dync -= logf(dynLS[s * D + d]);
        float initc = -8.0f * LOG2PI;
        for (int d = 0; d < D; d++) initc -= init_ls[s * D + d];
        float m = -1e30f;
        for (int k = 0; k < K; k++) m = fmaxf(m, init_logits[k]);
        float sum = 0.0f;
        for (int k = 0; k < K; k++) sum += expf(init_logits[k] - m);
        g_params[OFF_C0 + s] = (init_logits[s] - m - logf(sum)) + initc + emc;
        g_params[OFF_CT + s] = emc + dync;
    }
}

// ---------- stage 1: one thread per (b,t) ----------
__global__ __launch_bounds__(256)
void stage1_kernel(const int*   __restrict__ ds,
                   const float* __restrict__ cont,
                   const float* __restrict__ obs)
{
    __shared__ __align__(16) float sP[P_TOTAL];
    const int tid = threadIdx.x;
    {
        const float4* src = reinterpret_cast<const float4*>(g_params);
        float4* dst = reinterpret_cast<float4*>(sP);
        #pragma unroll
        for (int i = 0; i < P_TOTAL / 4 / 256 + 1; i++) {
            int idx = tid + i * 256;
            if (idx < P_TOTAL / 4) dst[idx] = src[idx];
        }
    }
    __syncthreads();

    const int gid = blockIdx.x * 256 + tid;
    const int lane = tid & 31;
    const int b = gid / TT;
    const int t = gid - b * TT;
    const int s = ds[gid];

    // z_t packed into 8 f32x2 regs; front-batch obs loads for MLP
    ull z2[8];
    float4 ov[8];
    {
        const float4* z4 = reinterpret_cast<const float4*>(cont) + gid * 4;
        const float4* o4 = reinterpret_cast<const float4*>(obs) + gid * 8;
        float4 v0 = z4[0], v1 = z4[1], v2 = z4[2], v3 = z4[3];
        #pragma unroll
        for (int i = 0; i < 8; i++) ov[i] = o4[i];
        PACK2(z2[0], v0.x, v0.y); PACK2(z2[1], v0.z, v0.w);
        PACK2(z2[2], v1.x, v1.y); PACK2(z2[3], v1.z, v1.w);
        PACK2(z2[4], v2.x, v2.y); PACK2(z2[5], v2.z, v2.w);
        PACK2(z2[6], v3.x, v3.y); PACK2(z2[7], v3.z, v3.w);
    }

    // previous-step state via warp shuffle (lane l-1 holds gid-1's data)
    ull zp2[8];
    #pragma unroll
    for (int i = 0; i < 8; i++) zp2[i] = __shfl_up_sync(0xFFFFFFFFu, z2[i], 1);
    int sp = __shfl_up_sync(0xFFFFFFFFu, s, 1);
    if (lane == 0 && t > 0) {
        const float4* p4 = reinterpret_cast<const float4*>(cont) + (gid - 1) * 4;
        float4 v0 = p4[0], v1 = p4[1], v2 = p4[2], v3 = p4[3];
        PACK2(zp2[0], v0.x, v0.y); PACK2(zp2[1], v0.z, v0.w);
        PACK2(zp2[2], v1.x, v1.y); PACK2(zp2[3], v1.z, v1.w);
        PACK2(zp2[4], v2.x, v2.y); PACK2(zp2[5], v2.z, v2.w);
        PACK2(zp2[6], v3.x, v3.y); PACK2(zp2[7], v3.z, v3.w);
        sp = ds[gid - 1];
    }

    float accs = 0.0f;
    ull acc2; { float zf = 0.0f; PACK2(acc2, zf, zf); }
    float lp;

    // ---- emission (all t), packed over n-pairs, fully unrolled ----
    {
        const float* Cb = sP + OFF_C + s * ES;
        const ull* EA = reinterpret_cast<const ull*>(sP + OFF_EA + s * EA_S);
        const ull* EB = reinterpret_cast<const ull*>(sP + OFF_EB + s * EA_S);
        #pragma unroll
        for (int n4 = 0; n4 < 8; n4++) {
            float4 o = ov[n4];
            int n = n4 * 4;
            float nd0 = dot16n(Cb + n * 16, z2);
            float nd1 = dot16n(Cb + (n + 1) * 16, z2);
            ull o01, nd01, y01;
            PACK2(o01, o.x, o.y);
            PACK2(nd01, nd0, nd1);
            FMA2(y01, o01, EA[n4 * 2], EB[n4 * 2]);
            ADD2(y01, y01, nd01);
            FMA2(acc2, y01, y01, acc2);
            float nd2 = dot16n(Cb + (n + 2) * 16, z2);
            float nd3 = dot16n(Cb + (n + 3) * 16, z2);
            ull o23, nd23, y23;
            PACK2(o23, o.z, o.w);
            PACK2(nd23, nd2, nd3);
            FMA2(y23, o23, EA[n4 * 2 + 1], EB[n4 * 2 + 1]);
            ADD2(y23, y23, nd23);
            FMA2(acc2, y23, y23, acc2);
        }
    }

    if (t == 0) {
        lp = sP[OFF_C0 + s];
        const float2* Ib = reinterpret_cast<const float2*>(sP + OFF_IN) + s * DYP;
        const float* zf = reinterpret_cast<const float*>(z2);
        #pragma unroll
        for (int d = 0; d < D; d++) {
            float2 ab = Ib[d];
            float y = fmaf(zf[d], ab.x, ab.y);
            accs = fmaf(y, y, accs);
        }
    } else {
        lp = sP[OFF_CT + s] + sP[OFF_TR + sp * K + s];
        const float* Ab = sP + OFF_A + s * AS;
        const float2* Db = reinterpret_cast<const float2*>(sP + OFF_DY) + s * DYP;
        const float* zf = reinterpret_cast<const float*>(z2);
        #pragma unroll
        for (int d = 0; d < D; d++) {
            float2 ab = Db[d];
            float nd = dot16n(Ab + d * 16, zp2);
            float y = fmaf(zf[d], ab.x, ab.y) + nd;
            accs = fmaf(y, y, accs);
        }
    }

    float lo, hi; UNPACK2(lo, hi, acc2);
    g_lp[gid] = lp - 0.5f * ((accs + lo) + hi);
}

// ---------- stage 2: one warp per b ----------
__global__ __launch_bounds__(256)
void stage2_kernel(float* __restrict__ out)
{
    const int b = blockIdx.x * 8 + (threadIdx.x >> 5);
    const int lane = threadIdx.x & 31;
    const float* base = g_lp + b * TT;
    float v[7];
    #pragma unroll
    for (int k = 0; k < 7; k++) {
        int t = lane + k * 32;
        v[k] = (t < TT) ? base[t] : 0.0f;
    }
    float sum = ((v[0] + v[1]) + (v[2] + v[3])) + ((v[4] + v[5]) + v[6]);
    #pragma unroll
    for (int o = 16; o > 0; o >>= 1) sum += __shfl_xor_sync(0xFFFFFFFFu, sum, o);
    if (lane == 0) out[b] = sum;
}

extern "C" void kernel_launch(void* const* d_in, const int* in_sizes, int n_in,
                              void* d_out, int out_size)
{
    const int*   ds    = (const int*)  d_in[0];
    const float* cont  = (const float*)d_in[1];
    const float* obs   = (const float*)d_in[2];
    const float* il    = (const float*)d_in[3];
    const float* iloc  = (const float*)d_in[4];
    const float* ils   = (const float*)d_in[5];
    const float* trl   = (const float*)d_in[6];
    const float* dynM  = (const float*)d_in[7];
    const float* dynO  = (const float*)d_in[8];
    const float* dynS  = (const float*)d_in[9];
    const float* emM   = (const float*)d_in[10];
    const float* emO   = (const float*)d_in[11];
    const float* emS   = (const float*)d_in[12];
    float* out = (float*)d_out;

    prep_kernel<<<26, 256>>>(il, iloc, ils, trl, dynM, dynO, dynS, emM, emO, emS);
    stage1_kernel<<<BT / 256, 256>>>(ds, cont, obs);
    stage2_kernel<<<BB / 8, 256>>>(out);
}